// round 1
// baseline (speedup 1.0000x reference)
#include <cuda_runtime.h>
#include <cuda_fp16.h>

// Problem constants (fixed by the dataset)
#define T_STEPS 8
#define N_NODES 50000
#define E_EDGES 800000
#define DD 64

// -------- scratch (static __device__ arrays; no allocation allowed) --------
__device__ __half g_y[(size_t)T_STEPS * N_NODES * DD];   // 51.2 MB, fp16 y = x@W
__device__ int    g_counts[N_NODES];
__device__ int    g_offsets[N_NODES + 1];
__device__ int    g_cursor[N_NODES];
__device__ int2   g_edges[E_EDGES];                      // (src | t_act<<20, w bits), CSR by dst

// ---------------------------------------------------------------------------
__global__ void zero_counts_kernel() {
    int i = blockIdx.x * blockDim.x + threadIdx.x;
    if (i < N_NODES) g_counts[i] = 0;
}

__global__ void count_kernel(const int* __restrict__ edge_index) {
    int e = blockIdx.x * blockDim.x + threadIdx.x;
    if (e < E_EDGES) atomicAdd(&g_counts[edge_index[E_EDGES + e]], 1);
}

// Single-block chunked Hillis-Steele exclusive scan over counts -> offsets/cursor
__global__ void scan_kernel() {
    __shared__ int buf[1024];
    __shared__ int carry_s;
    int tid = threadIdx.x;
    if (tid == 0) carry_s = 0;
    __syncthreads();
    for (int base = 0; base < N_NODES; base += 1024) {
        int i = base + tid;
        int v = (i < N_NODES) ? g_counts[i] : 0;
        buf[tid] = v;
        __syncthreads();
        #pragma unroll
        for (int off = 1; off < 1024; off <<= 1) {
            int t = (tid >= off) ? buf[tid - off] : 0;
            __syncthreads();
            buf[tid] += t;
            __syncthreads();
        }
        int incl  = buf[tid];
        int carry = carry_s;
        if (i < N_NODES) {
            int excl = carry + incl - v;
            g_offsets[i] = excl;
            g_cursor[i]  = excl;
        }
        __syncthreads();
        if (tid == 1023) carry_s = carry + incl;
        __syncthreads();
    }
    if (tid == 0) g_offsets[N_NODES] = carry_s;
}

__global__ void fill_kernel(const int* __restrict__ edge_index,
                            const float* __restrict__ edge_time,
                            const float* __restrict__ node_time,
                            const float* __restrict__ edge_weight) {
    int e = blockIdx.x * blockDim.x + threadIdx.x;
    if (e >= E_EDGES) return;
    int   src = edge_index[e];
    int   dst = edge_index[E_EDGES + e];
    float et  = edge_time[e];
    int tact = 0;
    #pragma unroll
    for (int t = 0; t < T_STEPS; t++) tact += (node_time[t] < et) ? 1 : 0;
    int pos = atomicAdd(&g_cursor[dst], 1);
    g_edges[pos] = make_int2(src | (tact << 20), __float_as_int(edge_weight[e]));
}

// ---------------------------------------------------------------------------
// y = x @ W  (rows = T*N = 400000, K = 64, cols = 64), fp32 accumulate, fp16 store.
// Block: 256 threads, tile 64 rows x 64 cols, 4x4 register blocking.
__global__ __launch_bounds__(256) void gemm_kernel(const float* __restrict__ x,
                                                   const float* __restrict__ W) {
    __shared__ float xs[64 * 68];   // padded stride 68
    __shared__ float Ws[64 * 64];
    int tid  = threadIdx.x;
    int row0 = blockIdx.x * 64;

    // stage W (64x64) and the x tile (64x64), coalesced float4
    for (int i = tid; i < 64 * 16; i += 256)
        ((float4*)Ws)[i] = ((const float4*)W)[i];
    for (int i = tid; i < 64 * 16; i += 256) {
        int r = i >> 4, c4 = i & 15;
        float4 v = *(const float4*)(x + (size_t)(row0 + r) * DD + c4 * 4);
        *(float4*)(xs + r * 68 + c4 * 4) = v;
    }
    __syncthreads();

    int tx = tid & 15, ty = tid >> 4;   // thread computes rows ty*4..+3, cols tx*4..+3
    float acc[4][4] = {};
    #pragma unroll 8
    for (int k = 0; k < 64; k++) {
        float4 bv = *(const float4*)(Ws + k * 64 + tx * 4);
        #pragma unroll
        for (int j = 0; j < 4; j++) {
            float a = xs[(ty * 4 + j) * 68 + k];
            acc[j][0] += a * bv.x;
            acc[j][1] += a * bv.y;
            acc[j][2] += a * bv.z;
            acc[j][3] += a * bv.w;
        }
    }

    #pragma unroll
    for (int j = 0; j < 4; j++) {
        size_t r = (size_t)(row0 + ty * 4 + j);
        __half2 h0 = __floats2half2_rn(acc[j][0], acc[j][1]);
        __half2 h1 = __floats2half2_rn(acc[j][2], acc[j][3]);
        __half2* p = (__half2*)(g_y + r * DD + tx * 4);
        p[0] = h0;
        p[1] = h1;
    }
}

// ---------------------------------------------------------------------------
// Gather: one warp per dst node, all 8 timesteps accumulated together.
// Each lane owns 2 feature columns. Edge meta read once; y gathers predicated
// on t >= t_act (skips ~50% of traffic + never-active edges).
__global__ __launch_bounds__(256) void gather_kernel(const float* __restrict__ bias,
                                                     float* __restrict__ out) {
    int gwarp = (blockIdx.x * blockDim.x + threadIdx.x) >> 5;
    int lane  = threadIdx.x & 31;
    if (gwarp >= N_NODES) return;
    int node = gwarp;

    int off0 = g_offsets[node];
    int off1 = g_offsets[node + 1];

    float2 acc[T_STEPS];
    #pragma unroll
    for (int t = 0; t < T_STEPS; t++) { acc[t].x = 0.f; acc[t].y = 0.f; }

    for (int e = off0; e < off1; e++) {
        int2 m   = g_edges[e];              // broadcast load (warp-uniform)
        int tact = m.x >> 20;
        if (tact >= T_STEPS) continue;      // never active
        int   src = m.x & 0xFFFFF;
        float w   = __int_as_float(m.y);
        const __half* yp = g_y + src * DD + lane * 2;
        #pragma unroll
        for (int t = 0; t < T_STEPS; t++) {
            if (t >= tact) {
                __half2 h = *(const __half2*)(yp + t * (N_NODES * DD));
                float2  f = __half22float2(h);
                acc[t].x += w * f.x;
                acc[t].y += w * f.y;
            }
        }
    }

    float2 bb = *(const float2*)(bias + lane * 2);
    #pragma unroll
    for (int t = 0; t < T_STEPS; t++) {
        float2 o;
        o.x = acc[t].x + bb.x;
        o.y = acc[t].y + bb.y;
        *(float2*)(out + ((size_t)t * N_NODES + node) * DD + lane * 2) = o;
    }
}

// ---------------------------------------------------------------------------
extern "C" void kernel_launch(void* const* d_in, const int* in_sizes, int n_in,
                              void* d_out, int out_size) {
    const float* x           = (const float*)d_in[0];   // [T, N, 64]
    const int*   edge_index  = (const int*)  d_in[1];   // [2, E]
    const float* edge_time   = (const float*)d_in[2];   // [E]
    const float* node_time   = (const float*)d_in[3];   // [T]
    const float* edge_weight = (const float*)d_in[4];   // [E]
    const float* W           = (const float*)d_in[5];   // [64, 64]
    const float* bias        = (const float*)d_in[6];   // [64]
    float* out = (float*)d_out;                         // [T, N, 64]

    // 1) CSR by dst
    zero_counts_kernel<<<(N_NODES + 255) / 256, 256>>>();
    count_kernel<<<(E_EDGES + 255) / 256, 256>>>(edge_index);
    scan_kernel<<<1, 1024>>>();
    fill_kernel<<<(E_EDGES + 255) / 256, 256>>>(edge_index, edge_time, node_time, edge_weight);

    // 2) y = x @ W  (fp16 output)
    gemm_kernel<<<(T_STEPS * N_NODES) / 64, 256>>>(x, W);

    // 3) out[t, i] = b + sum_{e in CSR[i], t >= tact(e)} w_e * y[t, src_e]
    gather_kernel<<<(N_NODES * 32 + 255) / 256, 256>>>(bias, out);
}

// round 2
// speedup vs baseline: 1.6599x; 1.6599x over previous
#include <cuda_runtime.h>
#include <cuda_fp16.h>
#include <mma.h>

// Problem constants (fixed by the dataset)
#define T_STEPS 8
#define N_NODES 50000
#define E_EDGES 800000
#define DD 64
#define NPART ((N_NODES + 255) / 256)   // 196 scan partials

// -------- scratch (static __device__ arrays; no allocation allowed) --------
__device__ __half g_y[(size_t)T_STEPS * N_NODES * DD];   // 51.2 MB, fp16 y = x@W
__device__ int    g_counts[N_NODES];
__device__ int    g_offsets[N_NODES + 1];
__device__ int    g_cursor[N_NODES];
__device__ int    g_part[NPART];
__device__ int2   g_edges[E_EDGES];     // (src | t_act<<20, w bits), CSR by dst

// ---------------------------------------------------------------------------
__global__ void zero_counts_kernel() {
    int i = blockIdx.x * blockDim.x + threadIdx.x;
    if (i < N_NODES) g_counts[i] = 0;
}

__global__ void count_kernel(const int* __restrict__ edge_index) {
    int e = blockIdx.x * blockDim.x + threadIdx.x;
    if (e < E_EDGES) atomicAdd(&g_counts[edge_index[E_EDGES + e]], 1);
}

// ---- 3-phase device-wide exclusive scan over g_counts -> g_offsets/g_cursor
__device__ __forceinline__ int block_excl_scan_256(int v, int tid) {
    // returns exclusive scan of v over the 256-thread block
    __shared__ int wsum[8];
    int lane = tid & 31, wid = tid >> 5;
    int x = v;
    #pragma unroll
    for (int o = 1; o < 32; o <<= 1) {
        int y = __shfl_up_sync(0xffffffffu, x, o);
        if (lane >= o) x += y;
    }
    if (lane == 31) wsum[wid] = x;
    __syncthreads();
    if (tid == 0) {
        int a = 0;
        #pragma unroll
        for (int w = 0; w < 8; w++) { int t = wsum[w]; wsum[w] = a; a += t; }
    }
    __syncthreads();
    return wsum[wid] + x - v;
}

__global__ __launch_bounds__(256) void scan1_kernel() {
    int tid = threadIdx.x;
    int i = blockIdx.x * 256 + tid;
    int v = (i < N_NODES) ? g_counts[i] : 0;
    int excl = block_excl_scan_256(v, tid);
    if (i < N_NODES) g_offsets[i] = excl;   // local exclusive, base added in scan3
    if (tid == 255) g_part[blockIdx.x] = excl + v;
}

__global__ __launch_bounds__(256) void scan2_kernel() {
    int tid = threadIdx.x;
    int v = (tid < NPART) ? g_part[tid] : 0;
    int excl = block_excl_scan_256(v, tid);
    if (tid < NPART) g_part[tid] = excl;
    if (tid == NPART - 1) g_offsets[N_NODES] = excl + v;
}

__global__ __launch_bounds__(256) void scan3_kernel() {
    int i = blockIdx.x * 256 + threadIdx.x;
    if (i < N_NODES) {
        int off = g_offsets[i] + g_part[blockIdx.x];
        g_offsets[i] = off;
        g_cursor[i]  = off;
    }
}

// ---------------------------------------------------------------------------
__global__ void fill_kernel(const int* __restrict__ edge_index,
                            const float* __restrict__ edge_time,
                            const float* __restrict__ node_time,
                            const float* __restrict__ edge_weight) {
    int e = blockIdx.x * blockDim.x + threadIdx.x;
    if (e >= E_EDGES) return;
    int   src = edge_index[e];
    int   dst = edge_index[E_EDGES + e];
    float et  = edge_time[e];
    int tact = 0;
    #pragma unroll
    for (int t = 0; t < T_STEPS; t++) tact += (__ldg(&node_time[t]) < et) ? 1 : 0;
    int pos = atomicAdd(&g_cursor[dst], 1);
    g_edges[pos] = make_int2(src | (tact << 20), __float_as_int(edge_weight[e]));
}

// ---------------------------------------------------------------------------
// y = x @ W via wmma (HMMA): 256 threads = 8 warps, 128 rows/block.
// x tile + W staged in smem as fp16 (padded ldm=80 halfs), fp32 accumulate,
// fp16 fragment store straight to g_y.
__global__ __launch_bounds__(256) void gemm_wmma_kernel(const float* __restrict__ x,
                                                        const float* __restrict__ W) {
    using namespace nvcuda;
    __shared__ __half xh[128 * 80];
    __shared__ __half Wh[64 * 80];
    int tid  = threadIdx.x;
    int warp = tid >> 5;
    size_t row0 = (size_t)blockIdx.x * 128;

    // stage W (64x64) as half
    for (int i = tid; i < 64 * 16; i += 256) {
        int r = i >> 4, c = (i & 15) * 4;
        float4 v = ((const float4*)W)[i];
        __half2* p = (__half2*)(Wh + r * 80 + c);
        p[0] = __floats2half2_rn(v.x, v.y);
        p[1] = __floats2half2_rn(v.z, v.w);
    }
    // stage x tile (128x64) as half
    for (int i = tid; i < 128 * 16; i += 256) {
        int r = i >> 4, c = (i & 15) * 4;
        float4 v = *(const float4*)(x + (row0 + r) * DD + c);
        __half2* p = (__half2*)(xh + r * 80 + c);
        p[0] = __floats2half2_rn(v.x, v.y);
        p[1] = __floats2half2_rn(v.z, v.w);
    }
    __syncthreads();

    wmma::fragment<wmma::accumulator, 16, 16, 16, float> acc[4];
    #pragma unroll
    for (int n = 0; n < 4; n++) wmma::fill_fragment(acc[n], 0.0f);

    #pragma unroll
    for (int k = 0; k < 4; k++) {
        wmma::fragment<wmma::matrix_a, 16, 16, 16, __half, wmma::row_major> af;
        wmma::load_matrix_sync(af, xh + (warp * 16) * 80 + k * 16, 80);
        #pragma unroll
        for (int n = 0; n < 4; n++) {
            wmma::fragment<wmma::matrix_b, 16, 16, 16, __half, wmma::row_major> bf;
            wmma::load_matrix_sync(bf, Wh + (k * 16) * 80 + n * 16, 80);
            wmma::mma_sync(acc[n], af, bf, acc[n]);
        }
    }

    #pragma unroll
    for (int n = 0; n < 4; n++) {
        wmma::fragment<wmma::accumulator, 16, 16, 16, __half> hacc;
        #pragma unroll
        for (int i = 0; i < hacc.num_elements; i++)
            hacc.x[i] = __float2half(acc[n].x[i]);
        wmma::store_matrix_sync(g_y + (row0 + warp * 16) * DD + n * 16,
                                hacc, DD, wmma::mem_row_major);
    }
}

// ---------------------------------------------------------------------------
// Gather: one warp per dst node, all 8 timesteps together, lane owns 2 cols.
// Straight-line body (no continue) + 2x edge unroll for MLP.
__device__ __forceinline__ void gather_body(int2 m, int lane, float2 acc[T_STEPS]) {
    int   tact = m.x >> 20;                 // 8 => never active; predicates kill all loads
    int   src  = m.x & 0xFFFFF;
    float w    = __int_as_float(m.y);
    const __half2* yp = (const __half2*)(g_y + (size_t)src * DD) + lane;
    #pragma unroll
    for (int t = 0; t < T_STEPS; t++) {
        if (t >= tact) {
            __half2 h = yp[t * (N_NODES * DD / 2)];
            float2  f = __half22float2(h);
            acc[t].x += w * f.x;
            acc[t].y += w * f.y;
        }
    }
}

__global__ __launch_bounds__(256) void gather_kernel(const float* __restrict__ bias,
                                                     float* __restrict__ out) {
    int gwarp = (blockIdx.x * blockDim.x + threadIdx.x) >> 5;
    int lane  = threadIdx.x & 31;
    if (gwarp >= N_NODES) return;
    int node = gwarp;

    int off0 = g_offsets[node];
    int off1 = g_offsets[node + 1];

    float2 acc[T_STEPS];
    #pragma unroll
    for (int t = 0; t < T_STEPS; t++) { acc[t].x = 0.f; acc[t].y = 0.f; }

    int e = off0;
    for (; e + 1 < off1; e += 2) {
        int2 m0 = g_edges[e];
        int2 m1 = g_edges[e + 1];
        gather_body(m0, lane, acc);
        gather_body(m1, lane, acc);
    }
    if (e < off1) gather_body(g_edges[e], lane, acc);

    float2 bb = *(const float2*)(bias + lane * 2);
    #pragma unroll
    for (int t = 0; t < T_STEPS; t++) {
        float2 o;
        o.x = acc[t].x + bb.x;
        o.y = acc[t].y + bb.y;
        *(float2*)(out + ((size_t)t * N_NODES + node) * DD + lane * 2) = o;
    }
}

// ---------------------------------------------------------------------------
extern "C" void kernel_launch(void* const* d_in, const int* in_sizes, int n_in,
                              void* d_out, int out_size) {
    const float* x           = (const float*)d_in[0];   // [T, N, 64]
    const int*   edge_index  = (const int*)  d_in[1];   // [2, E]
    const float* edge_time   = (const float*)d_in[2];   // [E]
    const float* node_time   = (const float*)d_in[3];   // [T]
    const float* edge_weight = (const float*)d_in[4];   // [E]
    const float* W           = (const float*)d_in[5];   // [64, 64]
    const float* bias        = (const float*)d_in[6];   // [64]
    float* out = (float*)d_out;                         // [T, N, 64]

    // 1) CSR by dst
    zero_counts_kernel<<<(N_NODES + 255) / 256, 256>>>();
    count_kernel<<<(E_EDGES + 255) / 256, 256>>>(edge_index);
    scan1_kernel<<<NPART, 256>>>();
    scan2_kernel<<<1, 256>>>();
    scan3_kernel<<<NPART, 256>>>();
    fill_kernel<<<(E_EDGES + 255) / 256, 256>>>(edge_index, edge_time, node_time, edge_weight);

    // 2) y = x @ W  (tensor cores, fp16 output)
    gemm_wmma_kernel<<<(T_STEPS * N_NODES) / 128, 256>>>(x, W);

    // 3) out[t, i] = b + sum_{e in CSR[i], t >= tact(e)} w_e * y[t, src_e]
    gather_kernel<<<(N_NODES * 32 + 255) / 256, 256>>>(bias, out);
}